// round 8
// baseline (speedup 1.0000x reference)
#include <cuda_runtime.h>
#include <math.h>

#define H_    192
#define W_    320
#define HW_   (H_*W_)
#define EPS_  1e-5f
#define INVD  (1.0f/507.0f)

#define HB     16               // output rows per CTA
#define NHB    12               // 192/16
#define NDH    8                // d's per half
#define NDCTA  16               // d's per CTA
#define GRIDX  20               // 20*16 = 320 d values, zero waste
#define NT     640              // threads: (half, x)
#define TROWS  (HB+12)          // 28 tile rows
#define PLW    348              // plane row width: 6+320+12(gap)+10 pad

// ---------------- device scratch ----------------
__device__ float  g_hL[HW_];                  // horiz 13-tap sum of L (3ch)
__device__ float  g_hR1[HW_];                 // of R
__device__ float  g_hR2[HW_];                 // of R^2
__device__ float2 g_AB[HW_];                  // (h,v): a, b
__device__ float  g_SL[HW_];                  // (h,w): patch sum of L
__device__ unsigned long long g_best[HW_];    // packed (enc(score) << 32) | (W-1-v)
__device__ float  g_scale;                    // fx * baseline

// ---------------- prep: horizontal 13-tap box sums + scale + best-init ----------------
__global__ void k_hbox(const float* __restrict__ L, const float* __restrict__ R,
                       const float* __restrict__ li,
                       const float* __restrict__ le,
                       const float* __restrict__ re) {
    int p = blockIdx.x * blockDim.x + threadIdx.x;
    if (p < HW_) {
        int x = p % W_;
        float hl = 0.f, r1 = 0.f, r2 = 0.f;
        #pragma unroll
        for (int dx = -6; dx <= 6; ++dx) {
            int xx = x + dx;
            if ((unsigned)xx < (unsigned)W_) {
                float l0 = L[p + dx], l1 = L[p + dx + HW_], l2 = L[p + dx + 2*HW_];
                float q0 = R[p + dx], q1 = R[p + dx + HW_], q2 = R[p + dx + 2*HW_];
                hl += l0 + l1 + l2;
                r1 += q0 + q1 + q2;
                r2 += q0*q0 + q1*q1 + q2*q2;
            }
        }
        g_hL[p] = hl; g_hR1[p] = r1; g_hR2[p] = r2;
        g_best[p] = 0ull;
    }
    if (p == 0) {
        float a[4][8];
        for (int i = 0; i < 4; ++i)
            for (int j = 0; j < 4; ++j) {
                a[i][j]     = le[i*4 + j];
                a[i][j + 4] = (i == j) ? 1.f : 0.f;
            }
        for (int c = 0; c < 4; ++c) {
            int piv = c; float mx = fabsf(a[c][c]);
            for (int r = c + 1; r < 4; ++r)
                if (fabsf(a[r][c]) > mx) { mx = fabsf(a[r][c]); piv = r; }
            if (piv != c)
                for (int j = 0; j < 8; ++j) { float t = a[c][j]; a[c][j] = a[piv][j]; a[piv][j] = t; }
            float inv = 1.f / a[c][c];
            for (int j = 0; j < 8; ++j) a[c][j] *= inv;
            for (int r = 0; r < 4; ++r) {
                if (r == c) continue;
                float f = a[r][c];
                for (int j = 0; j < 8; ++j) a[r][j] -= f * a[c][j];
            }
        }
        float t0 = 0.f, t1 = 0.f, t2 = 0.f;
        for (int k = 0; k < 4; ++k) {
            float ic = a[k][7];
            t0 += re[0*4 + k] * ic;
            t1 += re[1*4 + k] * ic;
            t2 += re[2*4 + k] * ic;
        }
        g_scale = li[0] * sqrtf(t0*t0 + t1*t1 + t2*t2);
    }
}

// ---------------- prep: vertical 13-tap + normalization terms ----------------
__global__ void k_vbox() {
    int p = blockIdx.x * blockDim.x + threadIdx.x;
    if (p >= HW_) return;
    int y = p / W_, x = p % W_;
    float sl = 0.f, s1 = 0.f, s2 = 0.f;
    #pragma unroll
    for (int dy = -6; dy <= 6; ++dy) {
        int yy = y + dy;
        if ((unsigned)yy < (unsigned)H_) {
            int q = yy * W_ + x;
            sl += g_hL[q]; s1 += g_hR1[q]; s2 += g_hR2[q];
        }
    }
    float var = fmaxf(s2 - s1 * s1 * INVD, 0.f);
    float a = 1.f / (sqrtf(var) + EPS_);
    g_AB[p] = make_float2(a, s1 * INVD * a);
    g_SL[p] = sl;
}

// ---------------- main: SoA R-planes, step-outer / d-inner ----------------
__global__ void __launch_bounds__(NT, 1) k_main(const float* __restrict__ L,
                                                const float* __restrict__ R) {
    extern __shared__ float sm[];
    float* rT0 = sm;                          // TROWS*W_ (channel 0)
    float* rT1 = sm + TROWS*W_;               // channel 1
    float* rT2 = sm + 2*TROWS*W_;             // channel 2
    float* pl  = sm + 3*TROWS*W_;             // 32 plane rows * PLW

    const int t    = threadIdx.x;
    const int half = t / W_;                 // 0 or 1
    const int x    = t % W_;
    const int h0   = blockIdx.y * HB;
    const int d0   = blockIdx.x * NDCTA + half * NDH;

    // cooperative R tile load into SoA planes (zero-pad outside rows)
    for (int i = t; i < TROWS * W_; i += NT) {
        int r = i / W_, xx = i % W_;
        int y = h0 - 6 + r;
        float c0 = 0.f, c1 = 0.f, c2 = 0.f;
        if ((unsigned)y < (unsigned)H_) {
            int p = y * W_ + xx;
            c0 = R[p]; c1 = R[p + HW_]; c2 = R[p + 2*HW_];
        }
        rT0[i] = c0; rT1[i] = c1; rT2[i] = c2;
    }
    // zero entire plane once: covers static pads AND all fixed wrap gaps
    for (int i = t; i < 32 * PLW; i += NT) pl[i] = 0.f;

    // per-d constants (fixed for the whole kernel)
    int vv[NDH], wp[NDH];
    #pragma unroll
    for (int d = 0; d < NDH; ++d) {
        int dd = d0 + d;
        int v = x + dd; if (v >= W_) v -= W_;
        vv[d] = v;
        int c = W_ - dd;                      // wrap column
        wp[d] = (x < c) ? (6 + x) : (18 + x); // seg1 [6,6+c), seg2 [18+c,338)
    }

    // hoist SL (d-independent)
    float SLr[HB];
    #pragma unroll
    for (int j = 0; j < HB; ++j) SLr[j] = g_SL[(h0 + j) * W_ + x];

    float bestS[HB]; int bestV[HB];
    #pragma unroll
    for (int j = 0; j < HB; ++j) { bestS[j] = -1e30f; bestV[j] = 0; }

    float ring[NDH][13];
    float V[NDH];
    #pragma unroll
    for (int d = 0; d < NDH; ++d) {
        V[d] = 0.f;
        #pragma unroll
        for (int k = 0; k < 13; ++k) ring[d][k] = 0.f;
    }

    __syncthreads();

    #pragma unroll
    for (int step = 0; step < TROWS; ++step) {
        // L row from gmem (L2-resident, coalesced, shared across all 8 d's)
        int y = h0 - 6 + step;
        float l0 = 0.f, l1 = 0.f, l2 = 0.f;
        if ((unsigned)y < (unsigned)H_) {
            int p = y * W_ + x;
            l0 = L[p]; l1 = L[p + HW_]; l2 = L[p + 2*HW_];
        }
        const int rowoff = step * W_;
        #pragma unroll
        for (int d = 0; d < NDH; ++d) {
            const int rv = rowoff + vv[d];
            float S = l0 * rT0[rv] + l1 * rT1[rv] + l2 * rT2[rv];   // 0 when y invalid
            V[d] += S - ring[d][step % 13];
            ring[d][step % 13] = S;
        }
        // V spans image rows [h-6, h+6] for output row h = h0 + step - 12
        const int hh = step - 12;             // compile-time
        if (hh >= 0) {
            const int pb = ((half * 2 + (hh & 1)) * NDH) * PLW;
            #pragma unroll
            for (int d = 0; d < NDH; ++d)
                pl[pb + d * PLW + wp[d]] = V[d];
            // prefetch AB for this row (latency hidden across the barrier)
            float2 ABr[NDH];
            #pragma unroll
            for (int d = 0; d < NDH; ++d)
                ABr[d] = g_AB[(h0 + hh) * W_ + vv[d]];
            __syncthreads();
            #pragma unroll
            for (int d = 0; d < NDH; ++d) {
                const float* q = &pl[pb + d * PLW + wp[d] - 6];
                float cr = q[0] + q[1] + q[2] + q[3] + q[4] + q[5] + q[6]
                         + q[7] + q[8] + q[9] + q[10] + q[11] + q[12];
                float s = cr * ABr[d].x - SLr[hh] * ABr[d].y;
                if (s > bestS[hh]) { bestS[hh] = s; bestV[hh] = vv[d]; }
            }
        }
    }

    // pack results
    unsigned long long mine[HB];
    #pragma unroll
    for (int j = 0; j < HB; ++j) {
        unsigned eb = __float_as_uint(bestS[j]);
        eb = (eb & 0x80000000u) ? ~eb : (eb | 0x80000000u);   // order-preserving
        mine[j] = ((unsigned long long)eb << 32)
                | (unsigned)(W_ - 1 - bestV[j]);              // ties -> smallest v
    }

    // intra-CTA half-merge through (now dead) plane buffer, then 1 atomic/pixel
    __syncthreads();
    unsigned long long* hbuf = (unsigned long long*)pl;       // 16*320*8 = 40,960 B
    if (half == 1) {
        #pragma unroll
        for (int j = 0; j < HB; ++j) hbuf[j * W_ + x] = mine[j];
    }
    __syncthreads();
    if (half == 0) {
        #pragma unroll
        for (int j = 0; j < HB; ++j) {
            unsigned long long o = hbuf[j * W_ + x];
            unsigned long long u = (o > mine[j]) ? o : mine[j];
            atomicMax(&g_best[(h0 + j) * W_ + x], u);
        }
    }
}

// ---------------- depth ----------------
__global__ void k_depth(float* __restrict__ out) {
    int p = blockIdx.x * blockDim.x + threadIdx.x;
    if (p >= HW_) return;
    unsigned long long u = g_best[p];
    int bv = W_ - 1 - (int)(u & 0xFFFFFFFFull);
    int w = p % W_;
    float disp = fabsf((float)bv - (float)w);
    disp = fmaxf(disp, 0.001f);
    out[p] = g_scale / disp;
}

// ---------------- launch ----------------
extern "C" void kernel_launch(void* const* d_in, const int* in_sizes, int n_in,
                              void* d_out, int out_size) {
    const float* L  = (const float*)d_in[0];
    const float* R  = (const float*)d_in[1];
    const float* li = (const float*)d_in[2];
    const float* le = (const float*)d_in[4];
    const float* re = (const float*)d_in[5];

    const int smemBytes = (3 * TROWS * W_ + 32 * PLW) * 4;   // 152,064 B
    cudaFuncSetAttribute(k_main, cudaFuncAttributeMaxDynamicSharedMemorySize, smemBytes);

    k_hbox<<<(HW_ + 255) / 256, 256>>>(L, R, li, le, re);
    k_vbox<<<(HW_ + 255) / 256, 256>>>();

    dim3 grid(GRIDX, NHB);
    k_main<<<grid, NT, smemBytes>>>(L, R);

    k_depth<<<(HW_ + 255) / 256, 256>>>((float*)d_out);
}

// round 9
// speedup vs baseline: 1.0439x; 1.0439x over previous
#include <cuda_runtime.h>
#include <math.h>

#define H_    192
#define W_    320
#define HW_   (H_*W_)
#define EPS_  1e-5f
#define INVD  (1.0f/507.0f)

#define HB     16               // output rows per CTA
#define NHB    12               // 192/16
#define NDH    8                // d's per half
#define NDCTA  16               // d's per CTA
#define GRIDX  20               // 20*16 = 320 d values, zero waste
#define NT     640              // threads: (half, x)
#define NSTEP  28               // HB+12 row steps
#define NSLOT  15               // circular R-row window
#define ROWF   (W_*3)           // floats per R row (960)
#define PLW    348              // plane row width: 6+320+12(gap)+10 pad

// ---------------- device scratch ----------------
__device__ float  g_hL[HW_];                  // horiz 13-tap sum of L (3ch)
__device__ float  g_hR1[HW_];                 // of R
__device__ float  g_hR2[HW_];                 // of R^2
__device__ float2 g_AB[HW_];                  // (h,v): a, b
__device__ float  g_SL[HW_];                  // (h,w): patch sum of L
__device__ unsigned long long g_best[HW_];    // packed (enc(score) << 32) | (W-1-v)
__device__ float  g_scale;                    // fx * baseline

// ---------------- prep: horizontal 13-tap box sums + scale + best-init ----------------
__global__ void k_hbox(const float* __restrict__ L, const float* __restrict__ R,
                       const float* __restrict__ li,
                       const float* __restrict__ le,
                       const float* __restrict__ re) {
    int p = blockIdx.x * blockDim.x + threadIdx.x;
    if (p < HW_) {
        int x = p % W_;
        float hl = 0.f, r1 = 0.f, r2 = 0.f;
        #pragma unroll
        for (int dx = -6; dx <= 6; ++dx) {
            int xx = x + dx;
            if ((unsigned)xx < (unsigned)W_) {
                float l0 = L[p + dx], l1 = L[p + dx + HW_], l2 = L[p + dx + 2*HW_];
                float q0 = R[p + dx], q1 = R[p + dx + HW_], q2 = R[p + dx + 2*HW_];
                hl += l0 + l1 + l2;
                r1 += q0 + q1 + q2;
                r2 += q0*q0 + q1*q1 + q2*q2;
            }
        }
        g_hL[p] = hl; g_hR1[p] = r1; g_hR2[p] = r2;
        g_best[p] = 0ull;
    }
    if (p == 0) {
        float a[4][8];
        for (int i = 0; i < 4; ++i)
            for (int j = 0; j < 4; ++j) {
                a[i][j]     = le[i*4 + j];
                a[i][j + 4] = (i == j) ? 1.f : 0.f;
            }
        for (int c = 0; c < 4; ++c) {
            int piv = c; float mx = fabsf(a[c][c]);
            for (int r = c + 1; r < 4; ++r)
                if (fabsf(a[r][c]) > mx) { mx = fabsf(a[r][c]); piv = r; }
            if (piv != c)
                for (int j = 0; j < 8; ++j) { float t = a[c][j]; a[c][j] = a[piv][j]; a[piv][j] = t; }
            float inv = 1.f / a[c][c];
            for (int j = 0; j < 8; ++j) a[c][j] *= inv;
            for (int r = 0; r < 4; ++r) {
                if (r == c) continue;
                float f = a[r][c];
                for (int j = 0; j < 8; ++j) a[r][j] -= f * a[c][j];
            }
        }
        float t0 = 0.f, t1 = 0.f, t2 = 0.f;
        for (int k = 0; k < 4; ++k) {
            float ic = a[k][7];
            t0 += re[0*4 + k] * ic;
            t1 += re[1*4 + k] * ic;
            t2 += re[2*4 + k] * ic;
        }
        g_scale = li[0] * sqrtf(t0*t0 + t1*t1 + t2*t2);
    }
}

// ---------------- prep: vertical 13-tap + normalization terms ----------------
__global__ void k_vbox() {
    int p = blockIdx.x * blockDim.x + threadIdx.x;
    if (p >= HW_) return;
    int y = p / W_, x = p % W_;
    float sl = 0.f, s1 = 0.f, s2 = 0.f;
    #pragma unroll
    for (int dy = -6; dy <= 6; ++dy) {
        int yy = y + dy;
        if ((unsigned)yy < (unsigned)H_) {
            int q = yy * W_ + x;
            sl += g_hL[q]; s1 += g_hR1[q]; s2 += g_hR2[q];
        }
    }
    float var = fmaxf(s2 - s1 * s1 * INVD, 0.f);
    float a = 1.f / (sqrtf(var) + EPS_);
    g_AB[p] = make_float2(a, s1 * INVD * a);
    g_SL[p] = sl;
}

// ---------------- main: ring-free (recompute), circular R window, 2 CTAs/SM ----------------
__global__ void __launch_bounds__(NT, 2) k_main(const float* __restrict__ L,
                                                const float* __restrict__ R) {
    extern __shared__ float sm[];
    float* rT = sm;                          // NSLOT rows * ROWF (circular)
    float* pl = sm + NSLOT * ROWF;           // 32 plane rows * PLW

    const int t    = threadIdx.x;
    const int half = t / W_;                 // 0 or 1
    const int x    = t % W_;
    const int h0   = blockIdx.y * HB;
    const int d0   = blockIdx.x * NDCTA + half * NDH;

    // zero planes (covers pads + all fixed wrap gaps)
    for (int i = t; i < 32 * PLW; i += NT) pl[i] = 0.f;

    // preload R row 0 into slot 0 (zero if outside image)
    {
        int y = h0 - 6;
        for (int i = t; i < ROWF; i += NT) {
            int ch = i / W_, xx = i % W_;
            float vsrc = 0.f;
            if ((unsigned)y < (unsigned)H_) vsrc = R[ch * HW_ + y * W_ + xx];
            rT[i] = vsrc;
        }
    }

    // per-d constants (fixed for the whole kernel)
    int vv[NDH], wp[NDH];
    #pragma unroll
    for (int d = 0; d < NDH; ++d) {
        int dd = d0 + d;
        int v = x + dd; if (v >= W_) v -= W_;
        vv[d] = v;
        int c = W_ - dd;                      // wrap column
        wp[d] = (x < c) ? (6 + x) : (18 + x); // seg1 [6,6+c), seg2 [18+c,338)
    }

    float SLr[HB];
    #pragma unroll
    for (int j = 0; j < HB; ++j) SLr[j] = g_SL[(h0 + j) * W_ + x];

    float bestS[HB]; int bestV[HB];
    #pragma unroll
    for (int j = 0; j < HB; ++j) { bestS[j] = -1e30f; bestV[j] = 0; }

    float V[NDH];
    #pragma unroll
    for (int d = 0; d < NDH; ++d) V[d] = 0.f;

    __syncthreads();   // row 0 + plane zeros visible

    #pragma unroll
    for (int s = 0; s < NSTEP; ++s) {
        // (a) prefetch R row s+1 into slot (s+1)%NSLOT (overlaps this step)
        if (s + 1 < NSTEP) {
            int y = h0 - 6 + (s + 1);
            float* dst = rT + ((s + 1) % NSLOT) * ROWF;   // compile-time slot
            for (int i = t; i < ROWF; i += NT) {
                int ch = i / W_, xx = i % W_;
                float vsrc = 0.f;
                if ((unsigned)y < (unsigned)H_) vsrc = R[ch * HW_ + y * W_ + xx];
                dst[i] = vsrc;
            }
        }

        // (b) incoming S at row s
        {
            int y = h0 - 6 + s;
            float l0 = 0.f, l1 = 0.f, l2 = 0.f;
            if ((unsigned)y < (unsigned)H_) {
                int p = y * W_ + x;
                l0 = L[p]; l1 = L[p + HW_]; l2 = L[p + 2*HW_];
            }
            const float* rs = rT + (s % NSLOT) * ROWF;    // compile-time slot
            #pragma unroll
            for (int d = 0; d < NDH; ++d) {
                int v = vv[d];
                V[d] += l0 * rs[v] + l1 * rs[W_ + v] + l2 * rs[2*W_ + v];
            }
        }
        // (c) outgoing S at row s-13 (recomputed; frees the 104-reg ring)
        if (s >= 13) {
            int y = h0 - 6 + (s - 13);
            float l0 = 0.f, l1 = 0.f, l2 = 0.f;
            if ((unsigned)y < (unsigned)H_) {
                int p = y * W_ + x;
                l0 = L[p]; l1 = L[p + HW_]; l2 = L[p + 2*HW_];
            }
            const float* rs = rT + ((s - 13) % NSLOT) * ROWF;  // compile-time slot
            #pragma unroll
            for (int d = 0; d < NDH; ++d) {
                int v = vv[d];
                V[d] -= l0 * rs[v] + l1 * rs[W_ + v] + l2 * rs[2*W_ + v];
            }
        }

        // (d) output row (V spans image rows [h-6, h+6], h = h0 + s - 12)
        const int hh = s - 12;                 // compile-time
        if (hh >= 0) {
            const int pb = ((half * 2 + (hh & 1)) * NDH) * PLW;
            #pragma unroll
            for (int d = 0; d < NDH; ++d)
                pl[pb + d * PLW + wp[d]] = V[d];
            float2 ABr[NDH];
            #pragma unroll
            for (int d = 0; d < NDH; ++d)
                ABr[d] = g_AB[(h0 + hh) * W_ + vv[d]];
            __syncthreads();                   // covers pl writes AND row prefetch
            #pragma unroll
            for (int d = 0; d < NDH; ++d) {
                const float* q = &pl[pb + d * PLW + wp[d] - 6];
                float cr = q[0] + q[1] + q[2] + q[3] + q[4] + q[5] + q[6]
                         + q[7] + q[8] + q[9] + q[10] + q[11] + q[12];
                float sc = cr * ABr[d].x - SLr[hh] * ABr[d].y;
                if (sc > bestS[hh]) { bestS[hh] = sc; bestV[hh] = vv[d]; }
            }
        } else {
            __syncthreads();                   // row prefetch visibility
        }
    }

    // one packed atomicMax per output pixel per (CTA, half)
    #pragma unroll
    for (int j = 0; j < HB; ++j) {
        unsigned eb = __float_as_uint(bestS[j]);
        eb = (eb & 0x80000000u) ? ~eb : (eb | 0x80000000u);   // order-preserving
        unsigned long long u = ((unsigned long long)eb << 32)
                             | (unsigned)(W_ - 1 - bestV[j]); // ties -> smallest v
        atomicMax(&g_best[(h0 + j) * W_ + x], u);
    }
}

// ---------------- depth ----------------
__global__ void k_depth(float* __restrict__ out) {
    int p = blockIdx.x * blockDim.x + threadIdx.x;
    if (p >= HW_) return;
    unsigned long long u = g_best[p];
    int bv = W_ - 1 - (int)(u & 0xFFFFFFFFull);
    int w = p % W_;
    float disp = fabsf((float)bv - (float)w);
    disp = fmaxf(disp, 0.001f);
    out[p] = g_scale / disp;
}

// ---------------- launch ----------------
extern "C" void kernel_launch(void* const* d_in, const int* in_sizes, int n_in,
                              void* d_out, int out_size) {
    const float* L  = (const float*)d_in[0];
    const float* R  = (const float*)d_in[1];
    const float* li = (const float*)d_in[2];
    const float* le = (const float*)d_in[4];
    const float* re = (const float*)d_in[5];

    const int smemBytes = (NSLOT * ROWF + 32 * PLW) * 4;   // 102,144 B -> 2 CTAs/SM
    cudaFuncSetAttribute(k_main, cudaFuncAttributeMaxDynamicSharedMemorySize, smemBytes);

    k_hbox<<<(HW_ + 255) / 256, 256>>>(L, R, li, le, re);
    k_vbox<<<(HW_ + 255) / 256, 256>>>();

    dim3 grid(GRIDX, NHB);
    k_main<<<grid, NT, smemBytes>>>(L, R);

    k_depth<<<(HW_ + 255) / 256, 256>>>((float*)d_out);
}